// round 1
// baseline (speedup 1.0000x reference)
#include <cuda_runtime.h>

#define NHEAD 16
#define SEQ 2048
#define DMODEL 1024
#define HDIM 64
#define BATCH 2
#define MTOT (BATCH * SEQ)   // 4096

// Scratch (device globals; no allocations allowed)
__device__ float g_Q[BATCH * NHEAD * SEQ * HDIM];
__device__ float g_K[BATCH * NHEAD * SEQ * HDIM];
__device__ float g_V[BATCH * NHEAD * SEQ * HDIM];
__device__ float g_ctx[MTOT * DMODEL];

// ---------------------------------------------------------------------------
// GEMM: C[M,N] = A[M,K] @ B[K,N] + bias[N]
// BM=BN=128, BK=16, 256 threads, 8x8 microtile per thread.
// HEADSPLIT=true stores C into [b, h, s, 64] layout (for Q/K/V).
// ---------------------------------------------------------------------------
template <bool HEADSPLIT>
__global__ __launch_bounds__(256) void gemm_bias_kernel(
    const float* __restrict__ A, const float* __restrict__ Bw,
    const float* __restrict__ bias, float* __restrict__ C,
    int M, int N, int Kd)
{
    const int BK = 16;
    __shared__ float As[BK][128];  // transposed A tile: As[k][m]
    __shared__ float Bs[BK][128];  // Bs[k][n]

    const int t  = threadIdx.x;
    const int tx = t & 15;
    const int ty = t >> 4;
    const int m0 = blockIdx.y * 128;
    const int n0 = blockIdx.x * 128;

    float acc[8][8];
#pragma unroll
    for (int i = 0; i < 8; i++)
#pragma unroll
        for (int j = 0; j < 8; j++) acc[i][j] = 0.f;

    for (int k0 = 0; k0 < Kd; k0 += BK) {
        // Load A tile 128x16 (512 float4), transpose into As
#pragma unroll
        for (int it = 0; it < 2; it++) {
            int f   = t + it * 256;
            int row = f >> 2;          // 0..127
            int kc  = (f & 3) * 4;     // 0,4,8,12
            float4 v = *(const float4*)&A[(m0 + row) * Kd + k0 + kc];
            As[kc + 0][row] = v.x;
            As[kc + 1][row] = v.y;
            As[kc + 2][row] = v.z;
            As[kc + 3][row] = v.w;
        }
        // Load B tile 16x128 (512 float4), direct
#pragma unroll
        for (int it = 0; it < 2; it++) {
            int f   = t + it * 256;
            int row = f >> 5;          // 0..15
            int c4  = (f & 31) * 4;    // 0..124
            *(float4*)&Bs[row][c4] = *(const float4*)&Bw[(k0 + row) * N + n0 + c4];
        }
        __syncthreads();

#pragma unroll
        for (int kk = 0; kk < BK; kk++) {
            float a[8], b[8];
#pragma unroll
            for (int i = 0; i < 8; i++) a[i] = As[kk][ty * 8 + i];
#pragma unroll
            for (int j = 0; j < 8; j++) b[j] = Bs[kk][tx * 8 + j];
#pragma unroll
            for (int i = 0; i < 8; i++)
#pragma unroll
                for (int j = 0; j < 8; j++) acc[i][j] += a[i] * b[j];
        }
        __syncthreads();
    }

    // Store
#pragma unroll
    for (int i = 0; i < 8; i++) {
        int m = m0 + ty * 8 + i;
#pragma unroll
        for (int j = 0; j < 8; j++) {
            int n = n0 + tx * 8 + j;
            float v = acc[i][j] + bias[n];
            if (HEADSPLIT) {
                int b  = m >> 11;      // / SEQ
                int s  = m & (SEQ - 1);
                int h  = n >> 6;       // / HDIM
                int kk = n & (HDIM - 1);
                C[(((b * NHEAD + h) * SEQ + s) << 6) + kk] = v;
            } else {
                C[m * N + n] = v;
            }
        }
    }
}

// ---------------------------------------------------------------------------
// Causal flash attention. One block = (batch b, head h, 64-row Q tile).
// 256 threads as 16x16, 4x4 microtiles. KV tiles of 64.
// smem: Qs transposed [d][r] (stride 64), KPs [d][c] stride 65 (reused for
// P transposed [c][r]), Vs [c][d] stride 64.
// ---------------------------------------------------------------------------
__global__ __launch_bounds__(256) void attn_kernel()
{
    extern __shared__ float smem[];
    float* Qs  = smem;                 // 64*64
    float* KPs = smem + 64 * 64;       // 64*65
    float* Vs  = KPs + 64 * 65;        // 64*64

    const int qt = blockIdx.x;
    const int h  = blockIdx.y;
    const int b  = blockIdx.z;
    const int t  = threadIdx.x;
    const int tx = t & 15;
    const int ty = t >> 4;
    const int q0 = qt * 64;

    const float* Qg = g_Q + ((b * NHEAD + h) * SEQ + q0) * HDIM;
    const float* Kg = g_K + ((b * NHEAD + h) * SEQ) * HDIM;
    const float* Vg = g_V + ((b * NHEAD + h) * SEQ) * HDIM;

    // Load Q tile (transposed: Qs[d][r])
#pragma unroll
    for (int it = 0; it < 4; it++) {
        int f  = t + it * 256;     // 1024 float4
        int r  = f >> 4;           // 0..63
        int d4 = (f & 15) * 4;
        float4 v = *(const float4*)&Qg[r * HDIM + d4];
        Qs[(d4 + 0) * 64 + r] = v.x;
        Qs[(d4 + 1) * 64 + r] = v.y;
        Qs[(d4 + 2) * 64 + r] = v.z;
        Qs[(d4 + 3) * 64 + r] = v.w;
    }

    float m_i[4], l_i[4], o[4][4];
#pragma unroll
    for (int i = 0; i < 4; i++) {
        m_i[i] = -1e30f;
        l_i[i] = 0.f;
#pragma unroll
        for (int j = 0; j < 4; j++) o[i][j] = 0.f;
    }

    for (int kt = 0; kt <= qt; kt++) {
        __syncthreads();  // prior PV / Q-load complete before refilling KPs,Vs
        const int c0 = kt * 64;
        // Load K tile transposed (KPs[d][c]) and V tile direct (Vs[c][d])
#pragma unroll
        for (int it = 0; it < 4; it++) {
            int f  = t + it * 256;
            int r  = f >> 4;
            int d4 = (f & 15) * 4;
            float4 kv = *(const float4*)&Kg[(c0 + r) * HDIM + d4];
            KPs[(d4 + 0) * 65 + r] = kv.x;
            KPs[(d4 + 1) * 65 + r] = kv.y;
            KPs[(d4 + 2) * 65 + r] = kv.z;
            KPs[(d4 + 3) * 65 + r] = kv.w;
            *(float4*)&Vs[r * 64 + d4] = *(const float4*)&Vg[(c0 + r) * HDIM + d4];
        }
        __syncthreads();

        // S = Q K^T * 1/8
        float s[4][4];
#pragma unroll
        for (int i = 0; i < 4; i++)
#pragma unroll
            for (int j = 0; j < 4; j++) s[i][j] = 0.f;
        for (int d = 0; d < 64; d++) {
            float a[4], bb[4];
#pragma unroll
            for (int i = 0; i < 4; i++) a[i] = Qs[d * 64 + ty * 4 + i];
#pragma unroll
            for (int j = 0; j < 4; j++) bb[j] = KPs[d * 65 + tx * 4 + j];
#pragma unroll
            for (int i = 0; i < 4; i++)
#pragma unroll
                for (int j = 0; j < 4; j++) s[i][j] += a[i] * bb[j];
        }
#pragma unroll
        for (int i = 0; i < 4; i++)
#pragma unroll
            for (int j = 0; j < 4; j++) s[i][j] *= 0.125f;

        // Causal mask on diagonal tile
        if (kt == qt) {
#pragma unroll
            for (int i = 0; i < 4; i++)
#pragma unroll
                for (int j = 0; j < 4; j++)
                    if (c0 + tx * 4 + j > q0 + ty * 4 + i) s[i][j] = -1e30f;
        }

        // Online softmax update
        float p[4][4];
#pragma unroll
        for (int i = 0; i < 4; i++) {
            float rm = s[i][0];
#pragma unroll
            for (int j = 1; j < 4; j++) rm = fmaxf(rm, s[i][j]);
#pragma unroll
            for (int off = 8; off >= 1; off >>= 1)
                rm = fmaxf(rm, __shfl_xor_sync(0xffffffffu, rm, off));
            float m_new = fmaxf(m_i[i], rm);
            float rs = 0.f;
#pragma unroll
            for (int j = 0; j < 4; j++) {
                p[i][j] = __expf(s[i][j] - m_new);
                rs += p[i][j];
            }
#pragma unroll
            for (int off = 8; off >= 1; off >>= 1)
                rs += __shfl_xor_sync(0xffffffffu, rs, off);
            float sc = __expf(m_i[i] - m_new);
            l_i[i] = l_i[i] * sc + rs;
            m_i[i] = m_new;
#pragma unroll
            for (int j = 0; j < 4; j++) o[i][j] *= sc;
        }

        __syncthreads();  // all threads done reading K from KPs
        // Write P transposed: KPs[c][r]
#pragma unroll
        for (int i = 0; i < 4; i++)
#pragma unroll
            for (int j = 0; j < 4; j++)
                KPs[(tx * 4 + j) * 65 + ty * 4 + i] = p[i][j];
        __syncthreads();

        // O += P @ V
        for (int c = 0; c < 64; c++) {
            float pp[4], vv[4];
#pragma unroll
            for (int i = 0; i < 4; i++) pp[i] = KPs[c * 65 + ty * 4 + i];
#pragma unroll
            for (int j = 0; j < 4; j++) vv[j] = Vs[c * 64 + tx * 4 + j];
#pragma unroll
            for (int i = 0; i < 4; i++)
#pragma unroll
                for (int j = 0; j < 4; j++) o[i][j] += pp[i] * vv[j];
        }
    }

    // Epilogue: normalize and write into ctx [B, S, D] at column h*64
    float* Og = g_ctx + (b * SEQ + q0) * DMODEL + h * HDIM;
#pragma unroll
    for (int i = 0; i < 4; i++) {
        float inv = 1.f / l_i[i];
#pragma unroll
        for (int j = 0; j < 4; j++)
            Og[(ty * 4 + i) * DMODEL + tx * 4 + j] = o[i][j] * inv;
    }
}

// ---------------------------------------------------------------------------
extern "C" void kernel_launch(void* const* d_in, const int* in_sizes, int n_in,
                              void* d_out, int out_size)
{
    const float* dec = (const float*)d_in[0];
    const float* enc = (const float*)d_in[1];
    // d_in[2] = mask (causal tril; implemented analytically)
    const float* Wq = (const float*)d_in[3];
    const float* bq = (const float*)d_in[4];
    const float* Wk = (const float*)d_in[5];
    const float* bk = (const float*)d_in[6];
    const float* Wv = (const float*)d_in[7];
    const float* bv = (const float*)d_in[8];
    const float* Wo = (const float*)d_in[9];
    const float* bo = (const float*)d_in[10];

    float *Q, *K, *V, *ctx;
    cudaGetSymbolAddress((void**)&Q,   g_Q);
    cudaGetSymbolAddress((void**)&K,   g_K);
    cudaGetSymbolAddress((void**)&V,   g_V);
    cudaGetSymbolAddress((void**)&ctx, g_ctx);

    dim3 gg(DMODEL / 128, MTOT / 128);  // (8, 32)

    gemm_bias_kernel<true><<<gg, 256>>>(dec, Wq, bq, Q, MTOT, DMODEL, DMODEL);
    gemm_bias_kernel<true><<<gg, 256>>>(enc, Wk, bk, K, MTOT, DMODEL, DMODEL);
    gemm_bias_kernel<true><<<gg, 256>>>(enc, Wv, bv, V, MTOT, DMODEL, DMODEL);

    const int attn_smem = (64 * 64 + 64 * 65 + 64 * 64) * (int)sizeof(float);  // 49408
    cudaFuncSetAttribute(attn_kernel, cudaFuncAttributeMaxDynamicSharedMemorySize, attn_smem);
    attn_kernel<<<dim3(SEQ / 64, NHEAD, BATCH), 256, attn_smem>>>();

    gemm_bias_kernel<false><<<gg, 256>>>(ctx, Wo, bo, (float*)d_out, MTOT, DMODEL, DMODEL);
}

// round 3
// speedup vs baseline: 1.4360x; 1.4360x over previous
#include <cuda_runtime.h>
#include <cuda_bf16.h>
#include <cstdint>

#define NHEAD 16
#define SEQ 2048
#define DMODEL 1024
#define HDIM 64
#define BATCH 2
#define MTOT (BATCH * SEQ)   // 4096
#define NELEM_ACT (MTOT * DMODEL)   // 4194304
#define NELEM_W   (DMODEL * DMODEL) // 1048576

// ---------------------------------------------------------------------------
// Scratch (device globals; no allocations allowed)
// ---------------------------------------------------------------------------
__device__ float g_Q[BATCH * NHEAD * SEQ * HDIM];
__device__ float g_K[BATCH * NHEAD * SEQ * HDIM];
__device__ float g_V[BATCH * NHEAD * SEQ * HDIM];
__device__ float g_ctx[MTOT * DMODEL];

__device__ __align__(16) __nv_bfloat16 g_dec_hi[NELEM_ACT];
__device__ __align__(16) __nv_bfloat16 g_dec_lo[NELEM_ACT];
__device__ __align__(16) __nv_bfloat16 g_enc_hi[NELEM_ACT];
__device__ __align__(16) __nv_bfloat16 g_enc_lo[NELEM_ACT];
__device__ __align__(16) __nv_bfloat16 g_ctx_hi[NELEM_ACT];
__device__ __align__(16) __nv_bfloat16 g_ctx_lo[NELEM_ACT];
__device__ __align__(16) __nv_bfloat16 g_Wq_hi[NELEM_W];
__device__ __align__(16) __nv_bfloat16 g_Wq_lo[NELEM_W];
__device__ __align__(16) __nv_bfloat16 g_Wk_hi[NELEM_W];
__device__ __align__(16) __nv_bfloat16 g_Wk_lo[NELEM_W];
__device__ __align__(16) __nv_bfloat16 g_Wv_hi[NELEM_W];
__device__ __align__(16) __nv_bfloat16 g_Wv_lo[NELEM_W];
__device__ __align__(16) __nv_bfloat16 g_Wo_hi[NELEM_W];
__device__ __align__(16) __nv_bfloat16 g_Wo_lo[NELEM_W];

// ---------------------------------------------------------------------------
// Helpers
// ---------------------------------------------------------------------------
__device__ __forceinline__ uint32_t smem_to_u32(const void* smem_ptr) {
    uint32_t addr;
    asm("{ .reg .u64 tmp; cvta.to.shared.u64 tmp, %1; cvt.u32.u64 %0, tmp; }"
        : "=r"(addr) : "l"(smem_ptr));
    return addr;
}

__device__ __forceinline__ void ldsm4(uint32_t* r, uint32_t addr) {
    asm volatile("ldmatrix.sync.aligned.m8n8.x4.shared.b16 {%0,%1,%2,%3}, [%4];"
                 : "=r"(r[0]), "=r"(r[1]), "=r"(r[2]), "=r"(r[3]) : "r"(addr));
}

__device__ __forceinline__ void mma_bf16(float* c, const uint32_t* a,
                                         uint32_t b0, uint32_t b1) {
    asm volatile(
        "mma.sync.aligned.m16n8k16.row.col.f32.bf16.bf16.f32 "
        "{%0,%1,%2,%3}, {%4,%5,%6,%7}, {%8,%9}, {%0,%1,%2,%3};"
        : "+f"(c[0]), "+f"(c[1]), "+f"(c[2]), "+f"(c[3])
        : "r"(a[0]), "r"(a[1]), "r"(a[2]), "r"(a[3]), "r"(b0), "r"(b1));
}

#define CP_ASYNC16(dst, src) \
    asm volatile("cp.async.cg.shared.global [%0], [%1], 16;" :: "r"(dst), "l"(src) : "memory")
#define CP_COMMIT()  asm volatile("cp.async.commit_group;" ::: "memory")
#define CP_WAIT(n)   asm volatile("cp.async.wait_group %0;" :: "n"(n) : "memory")

// ---------------------------------------------------------------------------
// Split fp32 -> (hi, lo) bf16, elementwise (vectorized x4)
// ---------------------------------------------------------------------------
__global__ __launch_bounds__(256) void split_kernel(
    const float* __restrict__ in, __nv_bfloat16* __restrict__ hi,
    __nv_bfloat16* __restrict__ lo, int n4)
{
    int i = blockIdx.x * 256 + threadIdx.x;
    if (i >= n4) return;
    float4 v = ((const float4*)in)[i];
    __nv_bfloat16 h0 = __float2bfloat16_rn(v.x), h1 = __float2bfloat16_rn(v.y);
    __nv_bfloat16 h2 = __float2bfloat16_rn(v.z), h3 = __float2bfloat16_rn(v.w);
    __nv_bfloat16 l0 = __float2bfloat16_rn(v.x - __bfloat162float(h0));
    __nv_bfloat16 l1 = __float2bfloat16_rn(v.y - __bfloat162float(h1));
    __nv_bfloat16 l2 = __float2bfloat16_rn(v.z - __bfloat162float(h2));
    __nv_bfloat16 l3 = __float2bfloat16_rn(v.w - __bfloat162float(h3));
    __nv_bfloat162* hp = (__nv_bfloat162*)hi;
    __nv_bfloat162* lp = (__nv_bfloat162*)lo;
    hp[i * 2 + 0] = __halves2bfloat162(h0, h1);
    hp[i * 2 + 1] = __halves2bfloat162(h2, h3);
    lp[i * 2 + 0] = __halves2bfloat162(l0, l1);
    lp[i * 2 + 1] = __halves2bfloat162(l2, l3);
}

// ---------------------------------------------------------------------------
// Transpose W[K,N] (row-major) -> T[N,K] with hi/lo bf16 split. 1024x1024.
// ---------------------------------------------------------------------------
__global__ __launch_bounds__(256) void transpose_split_kernel(
    const float* __restrict__ W, __nv_bfloat16* __restrict__ Thi,
    __nv_bfloat16* __restrict__ Tlo)
{
    __shared__ float tile[32][33];
    const int tx = threadIdx.x, ty = threadIdx.y;
    const int x = blockIdx.x * 32 + tx;
    const int y0 = blockIdx.y * 32;
#pragma unroll
    for (int j = ty; j < 32; j += 8)
        tile[j][tx] = W[(size_t)(y0 + j) * DMODEL + x];
    __syncthreads();
    const int x2 = y0 + tx;            // k index in T
    const int y2 = blockIdx.x * 32;    // n base in T
#pragma unroll
    for (int j = ty; j < 32; j += 8) {
        float v = tile[tx][j];
        __nv_bfloat16 h = __float2bfloat16_rn(v);
        __nv_bfloat16 l = __float2bfloat16_rn(v - __bfloat162float(h));
        Thi[(size_t)(y2 + j) * DMODEL + x2] = h;
        Tlo[(size_t)(y2 + j) * DMODEL + x2] = l;
    }
}

// ---------------------------------------------------------------------------
// bf16x3 GEMM via mma.sync: C[4096,1024] = A @ B^T + bias
// A: hi/lo bf16 [M,1024] K-major. B: hi/lo bf16 [N,1024] K-major (W^T).
// CTA 128x128, BK=32, double-buffered cp.async, 8 warps (2x4), warp 64x32.
// smem tiles (per stage): Ahi, Alo, Bhi, Blo, each 128 rows x 64B, swizzled.
// ---------------------------------------------------------------------------
template <bool HEADSPLIT>
__global__ __launch_bounds__(256, 1) void gemm_x3_kernel(
    const __nv_bfloat16* __restrict__ Ahi, const __nv_bfloat16* __restrict__ Alo,
    const __nv_bfloat16* __restrict__ Bhi, const __nv_bfloat16* __restrict__ Blo,
    const float* __restrict__ bias, float* __restrict__ C)
{
    extern __shared__ __align__(1024) char smem[];
    const uint32_t sb = smem_to_u32(smem);
    const int t    = threadIdx.x;
    const int lane = t & 31;
    const int wid  = t >> 5;
    const int wm   = wid >> 2;     // 0..1
    const int wn   = wid & 3;      // 0..3
    const int m0 = blockIdx.y * 128;
    const int n0 = blockIdx.x * 128;

    const __nv_bfloat16* b0p = Ahi + (size_t)m0 * DMODEL;
    const __nv_bfloat16* b1p = Alo + (size_t)m0 * DMODEL;
    const __nv_bfloat16* b2p = Bhi + (size_t)n0 * DMODEL;
    const __nv_bfloat16* b3p = Blo + (size_t)n0 * DMODEL;

    // Load one 32-wide K chunk of all 4 tiles into a stage.
    auto load_chunk = [&](int chunk, int stage) {
#pragma unroll
        for (int tile = 0; tile < 4; tile++) {
            const __nv_bfloat16* src =
                (tile == 0) ? b0p : (tile == 1) ? b1p : (tile == 2) ? b2p : b3p;
#pragma unroll
            for (int it = 0; it < 2; it++) {
                const int idx = t + it * 256;        // 0..511
                const int row = idx >> 2;            // 0..127
                const int col = idx & 3;             // 16B chunk within 64B row
                const uint32_t pc  = (uint32_t)(col ^ ((row >> 1) & 3));
                const uint32_t dst = sb + (uint32_t)stage * 32768u +
                                     (uint32_t)tile * 8192u +
                                     (uint32_t)row * 64u + (pc << 4);
                CP_ASYNC16(dst, src + (size_t)row * DMODEL + chunk * 32 + col * 8);
            }
        }
        CP_COMMIT();
    };

    load_chunk(0, 0);
    load_chunk(1, 1);

    float acc[4][4][4];
#pragma unroll
    for (int mf = 0; mf < 4; mf++)
#pragma unroll
        for (int nf = 0; nf < 4; nf++)
#pragma unroll
            for (int r = 0; r < 4; r++) acc[mf][nf][r] = 0.f;

    const int lrow  = lane & 15;     // ldmatrix row within 16-row fragment
    const int lcolq = lane >> 4;     // 0/1: which 8-element k chunk

    for (int ch = 0; ch < 32; ch++) {
        const int st = ch & 1;
        if (ch < 30) CP_WAIT(1);
        else         CP_WAIT(0);
        __syncthreads();
        const uint32_t base = sb + (uint32_t)st * 32768u;

#pragma unroll
        for (int ks = 0; ks < 2; ks++) {
            uint32_t ahi[4][4], alo[4][4];
#pragma unroll
            for (int mf = 0; mf < 4; mf++) {
                const int row = wm * 64 + mf * 16 + lrow;
                const uint32_t pc  = (uint32_t)((ks * 2 + lcolq) ^ ((row >> 1) & 3));
                const uint32_t off = (uint32_t)row * 64u + (pc << 4);
                ldsm4(ahi[mf], base + off);            // Ahi tile at +0
                ldsm4(alo[mf], base + 8192u + off);    // Alo tile
            }
            uint32_t bhi[2][4], blo[2][4];
#pragma unroll
            for (int nq = 0; nq < 2; nq++) {
                const int row = wn * 32 + nq * 16 + lrow;
                const uint32_t pc  = (uint32_t)((ks * 2 + lcolq) ^ ((row >> 1) & 3));
                const uint32_t off = (uint32_t)row * 64u + (pc << 4);
                ldsm4(bhi[nq], base + 16384u + off);   // Bhi tile
                ldsm4(blo[nq], base + 24576u + off);   // Blo tile
            }
#pragma unroll
            for (int mf = 0; mf < 4; mf++)
#pragma unroll
                for (int nf = 0; nf < 4; nf++) {
                    const int nq = nf >> 1, hh = nf & 1;
                    mma_bf16(acc[mf][nf], ahi[mf], bhi[nq][hh], bhi[nq][hh + 2]);
                    mma_bf16(acc[mf][nf], ahi[mf], blo[nq][hh], blo[nq][hh + 2]);
                    mma_bf16(acc[mf][nf], alo[mf], bhi[nq][hh], bhi[nq][hh + 2]);
                }
        }
        __syncthreads();   // everyone done reading stage st
        if (ch + 2 < 32) load_chunk(ch + 2, st);
    }

    // Epilogue: bias add + store (optionally head-split)
    const int gm = m0 + wm * 64;
    const int gn = n0 + wn * 32;
    const int g  = lane >> 2;
    const int c2 = (lane & 3) * 2;
#pragma unroll
    for (int mf = 0; mf < 4; mf++) {
#pragma unroll
        for (int nf = 0; nf < 4; nf++) {
            const int n = gn + nf * 8 + c2;
            const float bx = bias[n], by = bias[n + 1];
#pragma unroll
            for (int half = 0; half < 2; half++) {
                const int m = gm + mf * 16 + g + half * 8;
                float2 v = make_float2(acc[mf][nf][half * 2 + 0] + bx,
                                       acc[mf][nf][half * 2 + 1] + by);
                float* dst;
                if (HEADSPLIT) {
                    const int b = m >> 11, s = m & (SEQ - 1);
                    const int h = n >> 6, kk = n & (HDIM - 1);
                    dst = C + (((size_t)((b * NHEAD + h) * SEQ + s)) << 6) + kk;
                } else {
                    dst = C + (size_t)m * DMODEL + n;
                }
                *(float2*)dst = v;
            }
        }
    }
}

// ---------------------------------------------------------------------------
// Causal flash attention (unchanged from round 1). One block = (b, h, 64 rows).
// ---------------------------------------------------------------------------
__global__ __launch_bounds__(256) void attn_kernel()
{
    extern __shared__ float smemf[];
    float* Qs  = smemf;                 // 64*64
    float* KPs = smemf + 64 * 64;       // 64*65
    float* Vs  = KPs + 64 * 65;         // 64*64

    const int qt = blockIdx.x;
    const int h  = blockIdx.y;
    const int b  = blockIdx.z;
    const int t  = threadIdx.x;
    const int tx = t & 15;
    const int ty = t >> 4;
    const int q0 = qt * 64;

    const float* Qg = g_Q + ((b * NHEAD + h) * SEQ + q0) * HDIM;
    const float* Kg = g_K + ((b * NHEAD + h) * SEQ) * HDIM;
    const float* Vg = g_V + ((b * NHEAD + h) * SEQ) * HDIM;

#pragma unroll
    for (int it = 0; it < 4; it++) {
        int f  = t + it * 256;
        int r  = f >> 4;
        int d4 = (f & 15) * 4;
        float4 v = *(const float4*)&Qg[r * HDIM + d4];
        Qs[(d4 + 0) * 64 + r] = v.x;
        Qs[(d4 + 1) * 64 + r] = v.y;
        Qs[(d4 + 2) * 64 + r] = v.z;
        Qs[(d4 + 3) * 64 + r] = v.w;
    }

    float m_i[4], l_i[4], o[4][4];
#pragma unroll
    for (int i = 0; i < 4; i++) {
        m_i[i] = -1e30f;
        l_i[i] = 0.f;
#pragma unroll
        for (int j = 0; j < 4; j++) o[i][j] = 0.f;
    }

    for (int kt = 0; kt <= qt; kt++) {
        __syncthreads();
        const int c0 = kt * 64;
#pragma unroll
        for (int it = 0; it < 4; it++) {
            int f  = t + it * 256;
            int r  = f >> 4;
            int d4 = (f & 15) * 4;
            float4 kv = *(const float4*)&Kg[(c0 + r) * HDIM + d4];
            KPs[(d4 + 0) * 65 + r] = kv.x;
            KPs[(d4 + 1) * 65 + r] = kv.y;
            KPs[(d4 + 2) * 65 + r] = kv.z;
            KPs[(d4 + 3) * 65 + r] = kv.w;
            *(float4*)&Vs[r * 64 + d4] = *(const float4*)&Vg[(c0 + r) * HDIM + d4];
        }
        __syncthreads();

        float s[4][4];
#pragma unroll
        for (int i = 0; i < 4; i++)
#pragma unroll
            for (int j = 0; j < 4; j++) s[i][j] = 0.f;
        for (int d = 0; d < 64; d++) {
            float a[4], bb[4];
#pragma unroll
            for (int i = 0; i < 4; i++) a[i] = Qs[d * 64 + ty * 4 + i];
#pragma unroll
            for (int j = 0; j < 4; j++) bb[j] = KPs[d * 65 + tx * 4 + j];
#pragma unroll
            for (int i = 0; i < 4; i++)
#pragma unroll
                for (int j = 0; j < 4; j++) s[i][j] += a[i] * bb[j];
        }
#pragma unroll
        for (int i = 0; i < 4; i++)
#pragma unroll
            for (int j = 0; j < 4; j++) s[i][j] *= 0.125f;

        if (kt == qt) {
#pragma unroll
            for (int i = 0; i < 4; i++)
#pragma unroll
                for (int j = 0; j < 4; j++)
                    if (c0 + tx * 4 + j > q0 + ty * 4 + i) s[i][j] = -1e30f;
        }

        float p[4][4];
#pragma unroll
        for (int i = 0; i < 4; i++) {
            float rm = s[i][0];
#pragma unroll
            for (int j = 1; j < 4; j++) rm = fmaxf(rm, s[i][j]);
#pragma unroll
            for (int off = 8; off >= 1; off >>= 1)
                rm = fmaxf(rm, __shfl_xor_sync(0xffffffffu, rm, off));
            float m_new = fmaxf(m_i[i], rm);
            float rs = 0.f;
#pragma unroll
            for (int j = 0; j < 4; j++) {
                p[i][j] = __expf(s[i][j] - m_new);
                rs += p[i][j];
            }
#pragma unroll
            for (int off = 8; off >= 1; off >>= 1)
                rs += __shfl_xor_sync(0xffffffffu, rs, off);
            float sc = __expf(m_i[i] - m_new);
            l_i[i] = l_i[i] * sc + rs;
            m_i[i] = m_new;
#pragma unroll
            for (int j = 0; j < 4; j++) o[i][j] *= sc;
        }

        __syncthreads();
#pragma unroll
        for (int i = 0; i < 4; i++)
#pragma unroll
            for (int j = 0; j < 4; j++)
                KPs[(tx * 4 + j) * 65 + ty * 4 + i] = p[i][j];
        __syncthreads();

        for (int c = 0; c < 64; c++) {
            float pp[4], vv[4];
#pragma unroll
            for (int i = 0; i < 4; i++) pp[i] = KPs[c * 65 + ty * 4 + i];
#pragma unroll
            for (int j = 0; j < 4; j++) vv[j] = Vs[c * 64 + tx * 4 + j];
#pragma unroll
            for (int i = 0; i < 4; i++)
#pragma unroll
                for (int j = 0; j < 4; j++) o[i][j] += pp[i] * vv[j];
        }
    }

    float* Og = g_ctx + (b * SEQ + q0) * DMODEL + h * HDIM;
#pragma unroll
    for (int i = 0; i < 4; i++) {
        float inv = 1.f / l_i[i];
#pragma unroll
        for (int j = 0; j < 4; j++)
            Og[(ty * 4 + i) * DMODEL + tx * 4 + j] = o[i][j] * inv;
    }
}

// ---------------------------------------------------------------------------
extern "C" void kernel_launch(void* const* d_in, const int* in_sizes, int n_in,
                              void* d_out, int out_size)
{
    const float* dec = (const float*)d_in[0];
    const float* enc = (const float*)d_in[1];
    // d_in[2] = mask (causal tril; implemented analytically)
    const float* Wq = (const float*)d_in[3];
    const float* bq = (const float*)d_in[4];
    const float* Wk = (const float*)d_in[5];
    const float* bk = (const float*)d_in[6];
    const float* Wv = (const float*)d_in[7];
    const float* bv = (const float*)d_in[8];
    const float* Wo = (const float*)d_in[9];
    const float* bo = (const float*)d_in[10];

    float *Q, *K, *V, *ctx;
    cudaGetSymbolAddress((void**)&Q,   g_Q);
    cudaGetSymbolAddress((void**)&K,   g_K);
    cudaGetSymbolAddress((void**)&V,   g_V);
    cudaGetSymbolAddress((void**)&ctx, g_ctx);

    __nv_bfloat16 *dh, *dl, *eh, *el, *ch, *cl;
    __nv_bfloat16 *wqh, *wql, *wkh, *wkl, *wvh, *wvl, *woh, *wol;
    cudaGetSymbolAddress((void**)&dh,  g_dec_hi);
    cudaGetSymbolAddress((void**)&dl,  g_dec_lo);
    cudaGetSymbolAddress((void**)&eh,  g_enc_hi);
    cudaGetSymbolAddress((void**)&el,  g_enc_lo);
    cudaGetSymbolAddress((void**)&ch,  g_ctx_hi);
    cudaGetSymbolAddress((void**)&cl,  g_ctx_lo);
    cudaGetSymbolAddress((void**)&wqh, g_Wq_hi);
    cudaGetSymbolAddress((void**)&wql, g_Wq_lo);
    cudaGetSymbolAddress((void**)&wkh, g_Wk_hi);
    cudaGetSymbolAddress((void**)&wkl, g_Wk_lo);
    cudaGetSymbolAddress((void**)&wvh, g_Wv_hi);
    cudaGetSymbolAddress((void**)&wvl, g_Wv_lo);
    cudaGetSymbolAddress((void**)&woh, g_Wo_hi);
    cudaGetSymbolAddress((void**)&wol, g_Wo_lo);

    // Conversions
    split_kernel<<<NELEM_ACT / 1024, 256>>>(dec, dh, dl, NELEM_ACT / 4);
    split_kernel<<<NELEM_ACT / 1024, 256>>>(enc, eh, el, NELEM_ACT / 4);
    dim3 tb(32, 8), tg(32, 32);
    transpose_split_kernel<<<tg, tb>>>(Wq, wqh, wql);
    transpose_split_kernel<<<tg, tb>>>(Wk, wkh, wkl);
    transpose_split_kernel<<<tg, tb>>>(Wv, wvh, wvl);
    transpose_split_kernel<<<tg, tb>>>(Wo, woh, wol);

    // Tensor-core GEMMs (mma.sync bf16x3)
    const int gsm = 65536;
    cudaFuncSetAttribute(gemm_x3_kernel<true>,  cudaFuncAttributeMaxDynamicSharedMemorySize, gsm);
    cudaFuncSetAttribute(gemm_x3_kernel<false>, cudaFuncAttributeMaxDynamicSharedMemorySize, gsm);
    dim3 gg(DMODEL / 128, MTOT / 128);  // (8, 32)
    gemm_x3_kernel<true><<<gg, 256, gsm>>>(dh, dl, wqh, wql, bq, Q);
    gemm_x3_kernel<true><<<gg, 256, gsm>>>(eh, el, wkh, wkl, bk, K);
    gemm_x3_kernel<true><<<gg, 256, gsm>>>(eh, el, wvh, wvl, bv, V);

    // Attention
    const int attn_smem = (64 * 64 + 64 * 65 + 64 * 64) * (int)sizeof(float);
    cudaFuncSetAttribute(attn_kernel, cudaFuncAttributeMaxDynamicSharedMemorySize, attn_smem);
    attn_kernel<<<dim3(SEQ / 64, NHEAD, BATCH), 256, attn_smem>>>();

    // Output projection
    split_kernel<<<NELEM_ACT / 1024, 256>>>(ctx, ch, cl, NELEM_ACT / 4);
    gemm_x3_kernel<false><<<gg, 256, gsm>>>(ch, cl, woh, wol, bo, (float*)d_out);
}

// round 4
// speedup vs baseline: 2.7428x; 1.9100x over previous
#include <cuda_runtime.h>
#include <cuda_bf16.h>
#include <cstdint>

#define NHEAD 16
#define SEQ 2048
#define DMODEL 1024
#define HDIM 64
#define BATCH 2
#define MTOT (BATCH * SEQ)   // 4096
#define NELEM_ACT (MTOT * DMODEL)   // 4194304
#define NELEM_W   (DMODEL * DMODEL) // 1048576

// ---------------------------------------------------------------------------
// Scratch (device globals; no allocations allowed)
// ---------------------------------------------------------------------------
__device__ __align__(16) __nv_bfloat16 g_Qh[NELEM_ACT];
__device__ __align__(16) __nv_bfloat16 g_Ql[NELEM_ACT];
__device__ __align__(16) __nv_bfloat16 g_Kh[NELEM_ACT];
__device__ __align__(16) __nv_bfloat16 g_Kl[NELEM_ACT];
__device__ __align__(16) __nv_bfloat16 g_Vh[NELEM_ACT];
__device__ __align__(16) __nv_bfloat16 g_Vl[NELEM_ACT];
__device__ __align__(16) __nv_bfloat16 g_cth[NELEM_ACT];
__device__ __align__(16) __nv_bfloat16 g_ctl[NELEM_ACT];
__device__ __align__(16) __nv_bfloat16 g_dec_hi[NELEM_ACT];
__device__ __align__(16) __nv_bfloat16 g_dec_lo[NELEM_ACT];
__device__ __align__(16) __nv_bfloat16 g_enc_hi[NELEM_ACT];
__device__ __align__(16) __nv_bfloat16 g_enc_lo[NELEM_ACT];
__device__ __align__(16) __nv_bfloat16 g_Wq_hi[NELEM_W];
__device__ __align__(16) __nv_bfloat16 g_Wq_lo[NELEM_W];
__device__ __align__(16) __nv_bfloat16 g_Wk_hi[NELEM_W];
__device__ __align__(16) __nv_bfloat16 g_Wk_lo[NELEM_W];
__device__ __align__(16) __nv_bfloat16 g_Wv_hi[NELEM_W];
__device__ __align__(16) __nv_bfloat16 g_Wv_lo[NELEM_W];
__device__ __align__(16) __nv_bfloat16 g_Wo_hi[NELEM_W];
__device__ __align__(16) __nv_bfloat16 g_Wo_lo[NELEM_W];

// ---------------------------------------------------------------------------
// Helpers
// ---------------------------------------------------------------------------
__device__ __forceinline__ uint32_t smem_to_u32(const void* smem_ptr) {
    uint32_t addr;
    asm("{ .reg .u64 tmp; cvta.to.shared.u64 tmp, %1; cvt.u32.u64 %0, tmp; }"
        : "=r"(addr) : "l"(smem_ptr));
    return addr;
}

__device__ __forceinline__ void ldsm4(uint32_t* r, uint32_t addr) {
    asm volatile("ldmatrix.sync.aligned.m8n8.x4.shared.b16 {%0,%1,%2,%3}, [%4];"
                 : "=r"(r[0]), "=r"(r[1]), "=r"(r[2]), "=r"(r[3]) : "r"(addr));
}
__device__ __forceinline__ void ldsm4t(uint32_t* r, uint32_t addr) {
    asm volatile("ldmatrix.sync.aligned.m8n8.x4.trans.shared.b16 {%0,%1,%2,%3}, [%4];"
                 : "=r"(r[0]), "=r"(r[1]), "=r"(r[2]), "=r"(r[3]) : "r"(addr));
}

__device__ __forceinline__ void mma_bf16(float* c, const uint32_t* a,
                                         uint32_t b0, uint32_t b1) {
    asm volatile(
        "mma.sync.aligned.m16n8k16.row.col.f32.bf16.bf16.f32 "
        "{%0,%1,%2,%3}, {%4,%5,%6,%7}, {%8,%9}, {%0,%1,%2,%3};"
        : "+f"(c[0]), "+f"(c[1]), "+f"(c[2]), "+f"(c[3])
        : "r"(a[0]), "r"(a[1]), "r"(a[2]), "r"(a[3]), "r"(b0), "r"(b1));
}

__device__ __forceinline__ uint32_t packbf2(float x, float y) {
    __nv_bfloat162 h = __floats2bfloat162_rn(x, y);   // .x = low half
    return *(uint32_t*)&h;
}

#define CP_ASYNC16(dst, src) \
    asm volatile("cp.async.cg.shared.global [%0], [%1], 16;" :: "r"(dst), "l"(src) : "memory")
#define CP_COMMIT()  asm volatile("cp.async.commit_group;" ::: "memory")
#define CP_WAIT(n)   asm volatile("cp.async.wait_group %0;" :: "n"(n) : "memory")

// ---------------------------------------------------------------------------
// Split fp32 -> (hi, lo) bf16, elementwise (vectorized x4)
// ---------------------------------------------------------------------------
__global__ __launch_bounds__(256) void split_kernel(
    const float* __restrict__ in, __nv_bfloat16* __restrict__ hi,
    __nv_bfloat16* __restrict__ lo, int n4)
{
    int i = blockIdx.x * 256 + threadIdx.x;
    if (i >= n4) return;
    float4 v = ((const float4*)in)[i];
    __nv_bfloat16 h0 = __float2bfloat16_rn(v.x), h1 = __float2bfloat16_rn(v.y);
    __nv_bfloat16 h2 = __float2bfloat16_rn(v.z), h3 = __float2bfloat16_rn(v.w);
    __nv_bfloat16 l0 = __float2bfloat16_rn(v.x - __bfloat162float(h0));
    __nv_bfloat16 l1 = __float2bfloat16_rn(v.y - __bfloat162float(h1));
    __nv_bfloat16 l2 = __float2bfloat16_rn(v.z - __bfloat162float(h2));
    __nv_bfloat16 l3 = __float2bfloat16_rn(v.w - __bfloat162float(h3));
    __nv_bfloat162* hp = (__nv_bfloat162*)hi;
    __nv_bfloat162* lp = (__nv_bfloat162*)lo;
    hp[i * 2 + 0] = __halves2bfloat162(h0, h1);
    hp[i * 2 + 1] = __halves2bfloat162(h2, h3);
    lp[i * 2 + 0] = __halves2bfloat162(l0, l1);
    lp[i * 2 + 1] = __halves2bfloat162(l2, l3);
}

// ---------------------------------------------------------------------------
// Transpose W[K,N] -> T[N,K] with hi/lo bf16 split. 1024x1024.
// ---------------------------------------------------------------------------
__global__ __launch_bounds__(256) void transpose_split_kernel(
    const float* __restrict__ W, __nv_bfloat16* __restrict__ Thi,
    __nv_bfloat16* __restrict__ Tlo)
{
    __shared__ float tile[32][33];
    const int tx = threadIdx.x, ty = threadIdx.y;
    const int x = blockIdx.x * 32 + tx;
    const int y0 = blockIdx.y * 32;
#pragma unroll
    for (int j = ty; j < 32; j += 8)
        tile[j][tx] = W[(size_t)(y0 + j) * DMODEL + x];
    __syncthreads();
    const int x2 = y0 + tx;
    const int y2 = blockIdx.x * 32;
#pragma unroll
    for (int j = ty; j < 32; j += 8) {
        float v = tile[tx][j];
        __nv_bfloat16 h = __float2bfloat16_rn(v);
        __nv_bfloat16 l = __float2bfloat16_rn(v - __bfloat162float(h));
        Thi[(size_t)(y2 + j) * DMODEL + x2] = h;
        Tlo[(size_t)(y2 + j) * DMODEL + x2] = l;
    }
}

// ---------------------------------------------------------------------------
// bf16x3 GEMM via mma.sync: C[4096,1024] = A @ B^T + bias
// MODE 0: fp32 output, plain [M,N] layout (final projection).
// MODE 1: bf16 hi/lo output, head-split layout [b,h,s,64] (Q/K/V).
// ---------------------------------------------------------------------------
template <int MODE>
__global__ __launch_bounds__(256, 1) void gemm_x3_kernel(
    const __nv_bfloat16* __restrict__ Ahi, const __nv_bfloat16* __restrict__ Alo,
    const __nv_bfloat16* __restrict__ Bhi, const __nv_bfloat16* __restrict__ Blo,
    const float* __restrict__ bias, float* __restrict__ C,
    __nv_bfloat16* __restrict__ Chi, __nv_bfloat16* __restrict__ Clo)
{
    extern __shared__ __align__(1024) char smem[];
    const uint32_t sb = smem_to_u32(smem);
    const int t    = threadIdx.x;
    const int lane = t & 31;
    const int wid  = t >> 5;
    const int wm   = wid >> 2;
    const int wn   = wid & 3;
    const int m0 = blockIdx.y * 128;
    const int n0 = blockIdx.x * 128;

    const __nv_bfloat16* b0p = Ahi + (size_t)m0 * DMODEL;
    const __nv_bfloat16* b1p = Alo + (size_t)m0 * DMODEL;
    const __nv_bfloat16* b2p = Bhi + (size_t)n0 * DMODEL;
    const __nv_bfloat16* b3p = Blo + (size_t)n0 * DMODEL;

    auto load_chunk = [&](int chunk, int stage) {
#pragma unroll
        for (int tile = 0; tile < 4; tile++) {
            const __nv_bfloat16* src =
                (tile == 0) ? b0p : (tile == 1) ? b1p : (tile == 2) ? b2p : b3p;
#pragma unroll
            for (int it = 0; it < 2; it++) {
                const int idx = t + it * 256;
                const int row = idx >> 2;
                const int col = idx & 3;
                const uint32_t pc  = (uint32_t)(col ^ ((row >> 1) & 3));
                const uint32_t dst = sb + (uint32_t)stage * 32768u +
                                     (uint32_t)tile * 8192u +
                                     (uint32_t)row * 64u + (pc << 4);
                CP_ASYNC16(dst, src + (size_t)row * DMODEL + chunk * 32 + col * 8);
            }
        }
        CP_COMMIT();
    };

    load_chunk(0, 0);
    load_chunk(1, 1);

    float acc[4][4][4];
#pragma unroll
    for (int mf = 0; mf < 4; mf++)
#pragma unroll
        for (int nf = 0; nf < 4; nf++)
#pragma unroll
            for (int r = 0; r < 4; r++) acc[mf][nf][r] = 0.f;

    const int lrow  = lane & 15;
    const int lcolq = lane >> 4;

    for (int ch = 0; ch < 32; ch++) {
        const int st = ch & 1;
        if (ch < 30) CP_WAIT(1);
        else         CP_WAIT(0);
        __syncthreads();
        const uint32_t base = sb + (uint32_t)st * 32768u;

#pragma unroll
        for (int ks = 0; ks < 2; ks++) {
            uint32_t ahi[4][4], alo[4][4];
#pragma unroll
            for (int mf = 0; mf < 4; mf++) {
                const int row = wm * 64 + mf * 16 + lrow;
                const uint32_t pc  = (uint32_t)((ks * 2 + lcolq) ^ ((row >> 1) & 3));
                const uint32_t off = (uint32_t)row * 64u + (pc << 4);
                ldsm4(ahi[mf], base + off);
                ldsm4(alo[mf], base + 8192u + off);
            }
            uint32_t bhi[2][4], blo[2][4];
#pragma unroll
            for (int nq = 0; nq < 2; nq++) {
                const int row = wn * 32 + nq * 16 + lrow;
                const uint32_t pc  = (uint32_t)((ks * 2 + lcolq) ^ ((row >> 1) & 3));
                const uint32_t off = (uint32_t)row * 64u + (pc << 4);
                ldsm4(bhi[nq], base + 16384u + off);
                ldsm4(blo[nq], base + 24576u + off);
            }
#pragma unroll
            for (int mf = 0; mf < 4; mf++)
#pragma unroll
                for (int nf = 0; nf < 4; nf++) {
                    const int nq = nf >> 1, hh = nf & 1;
                    mma_bf16(acc[mf][nf], ahi[mf], bhi[nq][hh], bhi[nq][hh + 2]);
                    mma_bf16(acc[mf][nf], ahi[mf], blo[nq][hh], blo[nq][hh + 2]);
                    mma_bf16(acc[mf][nf], alo[mf], bhi[nq][hh], bhi[nq][hh + 2]);
                }
        }
        __syncthreads();
        if (ch + 2 < 32) load_chunk(ch + 2, st);
    }

    const int gm = m0 + wm * 64;
    const int gn = n0 + wn * 32;
    const int g  = lane >> 2;
    const int c2 = (lane & 3) * 2;
#pragma unroll
    for (int mf = 0; mf < 4; mf++) {
#pragma unroll
        for (int nf = 0; nf < 4; nf++) {
            const int n = gn + nf * 8 + c2;
            const float bx = bias[n], by = bias[n + 1];
#pragma unroll
            for (int half = 0; half < 2; half++) {
                const int m = gm + mf * 16 + g + half * 8;
                float v0 = acc[mf][nf][half * 2 + 0] + bx;
                float v1 = acc[mf][nf][half * 2 + 1] + by;
                if (MODE == 1) {
                    const int b = m >> 11, s = m & (SEQ - 1);
                    const int h = n >> 6, kk = n & (HDIM - 1);
                    const size_t idx = (((size_t)((b * NHEAD + h) * SEQ + s)) << 6) + kk;
                    float h0 = __bfloat162float(__float2bfloat16_rn(v0));
                    float h1 = __bfloat162float(__float2bfloat16_rn(v1));
                    *(uint32_t*)&Chi[idx] = packbf2(h0, h1);
                    *(uint32_t*)&Clo[idx] = packbf2(v0 - h0, v1 - h1);
                } else {
                    *(float2*)(C + (size_t)m * DMODEL + n) = make_float2(v0, v1);
                }
            }
        }
    }
}

// ---------------------------------------------------------------------------
// Tensor-core causal flash attention (bf16x3 via mma.sync).
// CTA = (128-row Q tile, head, batch), 8 warps x 16 rows, KV tiles of 64.
// Q hi/lo fragments register-resident; K/V hi/lo double-buffered via cp.async.
// Output ctx written as hi/lo bf16 into [b, s, 1024] layout.
// smem: Q (hi 16K, lo 16K) then 2 stages x {Khi 8K, Klo 8K, Vhi 8K, Vlo 8K}.
// ---------------------------------------------------------------------------
__global__ __launch_bounds__(256, 1) void attn_mma_kernel(
    const __nv_bfloat16* __restrict__ Qh, const __nv_bfloat16* __restrict__ Ql,
    const __nv_bfloat16* __restrict__ Kh, const __nv_bfloat16* __restrict__ Kl,
    const __nv_bfloat16* __restrict__ Vh, const __nv_bfloat16* __restrict__ Vl,
    __nv_bfloat16* __restrict__ Ch, __nv_bfloat16* __restrict__ Cl)
{
    extern __shared__ __align__(1024) char smem[];
    const uint32_t sb = smem_to_u32(smem);
    const int t    = threadIdx.x;
    const int lane = t & 31;
    const int w    = t >> 5;
    const int qt = blockIdx.x, h = blockIdx.y, b = blockIdx.z;
    const int q0 = qt * 128;

    const size_t headoff = (size_t)((b * NHEAD + h) * SEQ) * HDIM;
    const __nv_bfloat16* Qhp = Qh + headoff + (size_t)q0 * HDIM;
    const __nv_bfloat16* Qlp = Ql + headoff + (size_t)q0 * HDIM;
    const __nv_bfloat16* Khp = Kh + headoff;
    const __nv_bfloat16* Klp = Kl + headoff;
    const __nv_bfloat16* Vhp = Vh + headoff;
    const __nv_bfloat16* Vlp = Vl + headoff;

    // ---- Q tile loads (once): 128 rows x 128B, hi + lo ----
#pragma unroll
    for (int it = 0; it < 4; it++) {
        const int idx = t + it * 256;          // 0..1023
        const int row = idx >> 3;
        const int c   = idx & 7;
        const uint32_t pc = (uint32_t)(c ^ (row & 7));
        const uint32_t off = (uint32_t)row * 128u + (pc << 4);
        CP_ASYNC16(sb + off,          Qhp + (size_t)row * HDIM + c * 8);
        CP_ASYNC16(sb + 16384u + off, Qlp + (size_t)row * HDIM + c * 8);
    }
    CP_COMMIT();

    // ---- KV tile loader: stage = {Khi, Klo, Vhi, Vlo} each 64x128B ----
    auto load_kv = [&](int step, int stage) {
        const int c0 = step * 64;
        const __nv_bfloat16* srcs[4] = {
            Khp + (size_t)c0 * HDIM, Klp + (size_t)c0 * HDIM,
            Vhp + (size_t)c0 * HDIM, Vlp + (size_t)c0 * HDIM };
#pragma unroll
        for (int tile = 0; tile < 4; tile++) {
#pragma unroll
            for (int it = 0; it < 2; it++) {
                const int idx = t + it * 256;  // 0..511
                const int row = idx >> 3;
                const int c   = idx & 7;
                const uint32_t pc = (uint32_t)(c ^ (row & 7));
                const uint32_t dst = sb + 32768u + (uint32_t)stage * 32768u +
                                     (uint32_t)tile * 8192u +
                                     (uint32_t)row * 128u + (pc << 4);
                CP_ASYNC16(dst, srcs[tile] + (size_t)row * HDIM + c * 8);
            }
        }
        CP_COMMIT();
    };

    const int nkv = 2 * qt + 2;
    load_kv(0, 0);
    load_kv(1, 1);

    // ---- wait Q, build Q fragments (register resident) ----
    CP_WAIT(2);
    __syncthreads();
    uint32_t qhi[4][4], qlo[4][4];
#pragma unroll
    for (int kb = 0; kb < 4; kb++) {
        const int row = w * 16 + (lane & 15);
        const uint32_t pc = (uint32_t)((kb * 2 + (lane >> 4)) ^ (row & 7));
        const uint32_t off = (uint32_t)row * 128u + (pc << 4);
        ldsm4(qhi[kb], sb + off);
        ldsm4(qlo[kb], sb + 16384u + off);
    }

    float m_i[2] = {-1e30f, -1e30f};
    float l_i[2] = {0.f, 0.f};
    float o[8][4];
#pragma unroll
    for (int n8 = 0; n8 < 8; n8++)
#pragma unroll
        for (int r = 0; r < 4; r++) o[n8][r] = 0.f;

    const float SC = 0.18033688011112042f;   // log2(e) / 8
    const int g   = lane >> 2;
    const int c2  = (lane & 3) * 2;
    const int wrow = q0 + w * 16;            // warp's first row

    for (int i = 0; i < nkv; i++) {
        const int st = i & 1;
        if (i < nkv - 2) CP_WAIT(1);
        else             CP_WAIT(0);
        __syncthreads();
        const int c0 = i * 64;
        const bool skip = (c0 > wrow + 15);          // tile fully above diagonal
        if (!skip) {
            const uint32_t kvb = sb + 32768u + (uint32_t)st * 32768u;
            // ---- S = Q K^T (x3) ----
            float sacc[8][4];
#pragma unroll
            for (int n8 = 0; n8 < 8; n8++)
#pragma unroll
                for (int r = 0; r < 4; r++) sacc[n8][r] = 0.f;
#pragma unroll
            for (int kb = 0; kb < 4; kb++) {
#pragma unroll
                for (int nb = 0; nb < 4; nb++) {
                    uint32_t kf[4], kf2[4];
                    const int row = nb * 16 + (lane & 15);
                    const uint32_t pc = (uint32_t)((kb * 2 + (lane >> 4)) ^ (row & 7));
                    const uint32_t off = (uint32_t)row * 128u + (pc << 4);
                    ldsm4(kf,  kvb + off);            // Khi
                    ldsm4(kf2, kvb + 8192u + off);    // Klo
                    mma_bf16(sacc[2 * nb],     qhi[kb], kf[0],  kf[2]);
                    mma_bf16(sacc[2 * nb],     qhi[kb], kf2[0], kf2[2]);
                    mma_bf16(sacc[2 * nb],     qlo[kb], kf[0],  kf[2]);
                    mma_bf16(sacc[2 * nb + 1], qhi[kb], kf[1],  kf[3]);
                    mma_bf16(sacc[2 * nb + 1], qhi[kb], kf2[1], kf2[3]);
                    mma_bf16(sacc[2 * nb + 1], qlo[kb], kf[1],  kf[3]);
                }
            }
            // ---- scale + causal mask ----
            const bool needmask = (c0 + 63 > wrow);
            const int row0 = wrow + g, row1 = row0 + 8;
#pragma unroll
            for (int n8 = 0; n8 < 8; n8++) {
                const int col = c0 + n8 * 8 + c2;
#pragma unroll
                for (int r = 0; r < 4; r++) {
                    float v = sacc[n8][r] * SC;
                    if (needmask) {
                        const int cc = col + (r & 1);
                        const int rr = (r < 2) ? row0 : row1;
                        if (cc > rr) v = -1e30f;
                    }
                    sacc[n8][r] = v;
                }
            }
            // ---- online softmax (base-2 domain) ----
            float mx0 = -1e30f, mx1 = -1e30f;
#pragma unroll
            for (int n8 = 0; n8 < 8; n8++) {
                mx0 = fmaxf(mx0, fmaxf(sacc[n8][0], sacc[n8][1]));
                mx1 = fmaxf(mx1, fmaxf(sacc[n8][2], sacc[n8][3]));
            }
            mx0 = fmaxf(mx0, __shfl_xor_sync(0xffffffffu, mx0, 1));
            mx0 = fmaxf(mx0, __shfl_xor_sync(0xffffffffu, mx0, 2));
            mx1 = fmaxf(mx1, __shfl_xor_sync(0xffffffffu, mx1, 1));
            mx1 = fmaxf(mx1, __shfl_xor_sync(0xffffffffu, mx1, 2));
            const float mn0 = fmaxf(m_i[0], mx0);
            const float mn1 = fmaxf(m_i[1], mx1);
            const float sc0 = exp2f(m_i[0] - mn0);
            const float sc1 = exp2f(m_i[1] - mn1);
            float sum0 = 0.f, sum1 = 0.f;
#pragma unroll
            for (int n8 = 0; n8 < 8; n8++) {
                sacc[n8][0] = exp2f(sacc[n8][0] - mn0);
                sacc[n8][1] = exp2f(sacc[n8][1] - mn0);
                sacc[n8][2] = exp2f(sacc[n8][2] - mn1);
                sacc[n8][3] = exp2f(sacc[n8][3] - mn1);
                sum0 += sacc[n8][0] + sacc[n8][1];
                sum1 += sacc[n8][2] + sacc[n8][3];
            }
            sum0 += __shfl_xor_sync(0xffffffffu, sum0, 1);
            sum0 += __shfl_xor_sync(0xffffffffu, sum0, 2);
            sum1 += __shfl_xor_sync(0xffffffffu, sum1, 1);
            sum1 += __shfl_xor_sync(0xffffffffu, sum1, 2);
            l_i[0] = l_i[0] * sc0 + sum0;  m_i[0] = mn0;
            l_i[1] = l_i[1] * sc1 + sum1;  m_i[1] = mn1;
#pragma unroll
            for (int n8 = 0; n8 < 8; n8++) {
                o[n8][0] *= sc0; o[n8][1] *= sc0;
                o[n8][2] *= sc1; o[n8][3] *= sc1;
            }
            // ---- pack P hi/lo fragments (A operand, no shuffles) ----
            uint32_t phi[4][4], plo[4][4];
#pragma unroll
            for (int kb = 0; kb < 4; kb++) {
#pragma unroll
                for (int q = 0; q < 2; q++) {           // q=0: rows g; q=1: rows g+8
                    const float v0 = sacc[2 * kb][2 * q], v1 = sacc[2 * kb][2 * q + 1];
                    const float v2 = sacc[2 * kb + 1][2 * q], v3 = sacc[2 * kb + 1][2 * q + 1];
                    const float h0 = __bfloat162float(__float2bfloat16_rn(v0));
                    const float h1 = __bfloat162float(__float2bfloat16_rn(v1));
                    const float h2 = __bfloat162float(__float2bfloat16_rn(v2));
                    const float h3 = __bfloat162float(__float2bfloat16_rn(v3));
                    phi[kb][q]     = packbf2(h0, h1);
                    phi[kb][q + 2] = packbf2(h2, h3);
                    plo[kb][q]     = packbf2(v0 - h0, v1 - h1);
                    plo[kb][q + 2] = packbf2(v2 - h2, v3 - h3);
                }
            }
            // ---- O += P V (x3) ----
#pragma unroll
            for (int kb = 0; kb < 4; kb++) {
#pragma unroll
                for (int nb = 0; nb < 4; nb++) {
                    uint32_t vf[4], vf2[4];
                    const int row = kb * 16 + (lane & 15);
                    const uint32_t pc = (uint32_t)((nb * 2 + (lane >> 4)) ^ (row & 7));
                    const uint32_t off = (uint32_t)row * 128u + (pc << 4);
                    ldsm4t(vf,  kvb + 16384u + off);   // Vhi
                    ldsm4t(vf2, kvb + 24576u + off);   // Vlo
                    mma_bf16(o[2 * nb],     phi[kb], vf[0],  vf[1]);
                    mma_bf16(o[2 * nb],     phi[kb], vf2[0], vf2[1]);
                    mma_bf16(o[2 * nb],     plo[kb], vf[0],  vf[1]);
                    mma_bf16(o[2 * nb + 1], phi[kb], vf[2],  vf[3]);
                    mma_bf16(o[2 * nb + 1], phi[kb], vf2[2], vf2[3]);
                    mma_bf16(o[2 * nb + 1], plo[kb], vf[2],  vf[3]);
                }
            }
        }
        __syncthreads();
        if (i + 2 < nkv) load_kv(i + 2, st);
    }

    // ---- epilogue: normalize, split hi/lo, store to ctx [b, s, 1024] ----
    const float inv0 = 1.f / l_i[0];
    const float inv1 = 1.f / l_i[1];
    const int row0 = q0 + w * 16 + g;
    const size_t base0 = ((size_t)(b * SEQ + row0)) * DMODEL + h * HDIM;
    const size_t base1 = base0 + (size_t)8 * DMODEL;
#pragma unroll
    for (int n8 = 0; n8 < 8; n8++) {
        const int col = n8 * 8 + c2;
        float v0 = o[n8][0] * inv0, v1 = o[n8][1] * inv0;
        float v2 = o[n8][2] * inv1, v3 = o[n8][3] * inv1;
        float h0 = __bfloat162float(__float2bfloat16_rn(v0));
        float h1 = __bfloat162float(__float2bfloat16_rn(v1));
        float h2 = __bfloat162float(__float2bfloat16_rn(v2));
        float h3 = __bfloat162float(__float2bfloat16_rn(v3));
        *(uint32_t*)&Ch[base0 + col] = packbf2(h0, h1);
        *(uint32_t*)&Cl[base0 + col] = packbf2(v0 - h0, v1 - h1);
        *(uint32_t*)&Ch[base1 + col] = packbf2(h2, h3);
        *(uint32_t*)&Cl[base1 + col] = packbf2(v2 - h2, v3 - h3);
    }
}

// ---------------------------------------------------------------------------
extern "C" void kernel_launch(void* const* d_in, const int* in_sizes, int n_in,
                              void* d_out, int out_size)
{
    const float* dec = (const float*)d_in[0];
    const float* enc = (const float*)d_in[1];
    // d_in[2] = mask (causal tril; implemented analytically)
    const float* Wq = (const float*)d_in[3];
    const float* bq = (const float*)d_in[4];
    const float* Wk = (const float*)d_in[5];
    const float* bk = (const float*)d_in[6];
    const float* Wv = (const float*)d_in[7];
    const float* bv = (const float*)d_in[8];
    const float* Wo = (const float*)d_in[9];
    const float* bo = (const float*)d_in[10];

    __nv_bfloat16 *qh, *ql, *kh, *kl, *vh, *vl, *cth, *ctl;
    __nv_bfloat16 *dh, *dl, *eh, *el;
    __nv_bfloat16 *wqh, *wql, *wkh, *wkl, *wvh, *wvl, *woh, *wol;
    cudaGetSymbolAddress((void**)&qh,  g_Qh);
    cudaGetSymbolAddress((void**)&ql,  g_Ql);
    cudaGetSymbolAddress((void**)&kh,  g_Kh);
    cudaGetSymbolAddress((void**)&kl,  g_Kl);
    cudaGetSymbolAddress((void**)&vh,  g_Vh);
    cudaGetSymbolAddress((void**)&vl,  g_Vl);
    cudaGetSymbolAddress((void**)&cth, g_cth);
    cudaGetSymbolAddress((void**)&ctl, g_ctl);
    cudaGetSymbolAddress((void**)&dh,  g_dec_hi);
    cudaGetSymbolAddress((void**)&dl,  g_dec_lo);
    cudaGetSymbolAddress((void**)&eh,  g_enc_hi);
    cudaGetSymbolAddress((void**)&el,  g_enc_lo);
    cudaGetSymbolAddress((void**)&wqh, g_Wq_hi);
    cudaGetSymbolAddress((void**)&wql, g_Wq_lo);
    cudaGetSymbolAddress((void**)&wkh, g_Wk_hi);
    cudaGetSymbolAddress((void**)&wkl, g_Wk_lo);
    cudaGetSymbolAddress((void**)&wvh, g_Wv_hi);
    cudaGetSymbolAddress((void**)&wvl, g_Wv_lo);
    cudaGetSymbolAddress((void**)&woh, g_Wo_hi);
    cudaGetSymbolAddress((void**)&wol, g_Wo_lo);

    // Conversions
    split_kernel<<<NELEM_ACT / 1024, 256>>>(dec, dh, dl, NELEM_ACT / 4);
    split_kernel<<<NELEM_ACT / 1024, 256>>>(enc, eh, el, NELEM_ACT / 4);
    dim3 tb(32, 8), tg(32, 32);
    transpose_split_kernel<<<tg, tb>>>(Wq, wqh, wql);
    transpose_split_kernel<<<tg, tb>>>(Wk, wkh, wkl);
    transpose_split_kernel<<<tg, tb>>>(Wv, wvh, wvl);
    transpose_split_kernel<<<tg, tb>>>(Wo, woh, wol);

    // Projections (bf16 hi/lo head-split outputs)
    const int gsm = 65536;
    cudaFuncSetAttribute(gemm_x3_kernel<0>, cudaFuncAttributeMaxDynamicSharedMemorySize, gsm);
    cudaFuncSetAttribute(gemm_x3_kernel<1>, cudaFuncAttributeMaxDynamicSharedMemorySize, gsm);
    dim3 gg(DMODEL / 128, MTOT / 128);
    gemm_x3_kernel<1><<<gg, 256, gsm>>>(dh, dl, wqh, wql, bq, nullptr, qh, ql);
    gemm_x3_kernel<1><<<gg, 256, gsm>>>(eh, el, wkh, wkl, bk, nullptr, kh, kl);
    gemm_x3_kernel<1><<<gg, 256, gsm>>>(eh, el, wvh, wvl, bv, nullptr, vh, vl);

    // Tensor-core flash attention
    const int asm_bytes = 32768 + 2 * 32768;   // 96 KB
    cudaFuncSetAttribute(attn_mma_kernel, cudaFuncAttributeMaxDynamicSharedMemorySize, asm_bytes);
    attn_mma_kernel<<<dim3(SEQ / 128, NHEAD, BATCH), 256, asm_bytes>>>(
        qh, ql, kh, kl, vh, vl, cth, ctl);

    // Output projection
    gemm_x3_kernel<0><<<gg, 256, gsm>>>(cth, ctl, woh, wol, bo, (float*)d_out,
                                        nullptr, nullptr);
}

// round 5
// speedup vs baseline: 2.9201x; 1.0647x over previous
#include <cuda_runtime.h>
#include <cuda_bf16.h>
#include <cstdint>

#define NHEAD 16
#define SEQ 2048
#define DMODEL 1024
#define HDIM 64
#define BATCH 2
#define MTOT (BATCH * SEQ)   // 4096
#define NELEM_ACT (MTOT * DMODEL)   // 4194304
#define NELEM_W   (DMODEL * DMODEL) // 1048576

// ---------------------------------------------------------------------------
// Scratch (device globals; no allocations allowed)
// ---------------------------------------------------------------------------
__device__ __align__(16) __nv_bfloat16 g_Qh[NELEM_ACT];
__device__ __align__(16) __nv_bfloat16 g_Ql[NELEM_ACT];
__device__ __align__(16) __nv_bfloat16 g_Kh[NELEM_ACT];
__device__ __align__(16) __nv_bfloat16 g_Kl[NELEM_ACT];
__device__ __align__(16) __nv_bfloat16 g_Vh[NELEM_ACT];
__device__ __align__(16) __nv_bfloat16 g_Vl[NELEM_ACT];
__device__ __align__(16) __nv_bfloat16 g_cth[NELEM_ACT];
__device__ __align__(16) __nv_bfloat16 g_ctl[NELEM_ACT];
__device__ __align__(16) __nv_bfloat16 g_dec_hi[NELEM_ACT];
__device__ __align__(16) __nv_bfloat16 g_dec_lo[NELEM_ACT];
__device__ __align__(16) __nv_bfloat16 g_enc_hi[NELEM_ACT];
__device__ __align__(16) __nv_bfloat16 g_enc_lo[NELEM_ACT];
__device__ __align__(16) __nv_bfloat16 g_Wq_hi[NELEM_W];
__device__ __align__(16) __nv_bfloat16 g_Wq_lo[NELEM_W];
__device__ __align__(16) __nv_bfloat16 g_Wk_hi[NELEM_W];
__device__ __align__(16) __nv_bfloat16 g_Wk_lo[NELEM_W];
__device__ __align__(16) __nv_bfloat16 g_Wv_hi[NELEM_W];
__device__ __align__(16) __nv_bfloat16 g_Wv_lo[NELEM_W];
__device__ __align__(16) __nv_bfloat16 g_Wo_hi[NELEM_W];
__device__ __align__(16) __nv_bfloat16 g_Wo_lo[NELEM_W];

// ---------------------------------------------------------------------------
// Helpers
// ---------------------------------------------------------------------------
__device__ __forceinline__ uint32_t smem_to_u32(const void* smem_ptr) {
    uint32_t addr;
    asm("{ .reg .u64 tmp; cvta.to.shared.u64 tmp, %1; cvt.u32.u64 %0, tmp; }"
        : "=r"(addr) : "l"(smem_ptr));
    return addr;
}

__device__ __forceinline__ void ldsm4(uint32_t* r, uint32_t addr) {
    asm volatile("ldmatrix.sync.aligned.m8n8.x4.shared.b16 {%0,%1,%2,%3}, [%4];"
                 : "=r"(r[0]), "=r"(r[1]), "=r"(r[2]), "=r"(r[3]) : "r"(addr));
}
__device__ __forceinline__ void ldsm4t(uint32_t* r, uint32_t addr) {
    asm volatile("ldmatrix.sync.aligned.m8n8.x4.trans.shared.b16 {%0,%1,%2,%3}, [%4];"
                 : "=r"(r[0]), "=r"(r[1]), "=r"(r[2]), "=r"(r[3]) : "r"(addr));
}

__device__ __forceinline__ void mma_bf16(float* c, const uint32_t* a,
                                         uint32_t b0, uint32_t b1) {
    asm volatile(
        "mma.sync.aligned.m16n8k16.row.col.f32.bf16.bf16.f32 "
        "{%0,%1,%2,%3}, {%4,%5,%6,%7}, {%8,%9}, {%0,%1,%2,%3};"
        : "+f"(c[0]), "+f"(c[1]), "+f"(c[2]), "+f"(c[3])
        : "r"(a[0]), "r"(a[1]), "r"(a[2]), "r"(a[3]), "r"(b0), "r"(b1));
}

__device__ __forceinline__ uint32_t packbf2(float x, float y) {
    __nv_bfloat162 h = __floats2bfloat162_rn(x, y);
    return *(uint32_t*)&h;
}

#define CP_ASYNC16(dst, src) \
    asm volatile("cp.async.cg.shared.global [%0], [%1], 16;" :: "r"(dst), "l"(src) : "memory")
#define CP_COMMIT()  asm volatile("cp.async.commit_group;" ::: "memory")
#define CP_WAIT(n)   asm volatile("cp.async.wait_group %0;" :: "n"(n) : "memory")

// ---------------------------------------------------------------------------
// Fused split: fp32 -> (hi, lo) bf16 for dec and enc (blockIdx.y selects)
// ---------------------------------------------------------------------------
__global__ __launch_bounds__(256) void split2_kernel(
    const float* __restrict__ in0, __nv_bfloat16* __restrict__ hi0,
    __nv_bfloat16* __restrict__ lo0,
    const float* __restrict__ in1, __nv_bfloat16* __restrict__ hi1,
    __nv_bfloat16* __restrict__ lo1, int n4)
{
    const float* in = blockIdx.y ? in1 : in0;
    __nv_bfloat16* hi = blockIdx.y ? hi1 : hi0;
    __nv_bfloat16* lo = blockIdx.y ? lo1 : lo0;
    int i = blockIdx.x * 256 + threadIdx.x;
    if (i >= n4) return;
    float4 v = ((const float4*)in)[i];
    __nv_bfloat16 h0 = __float2bfloat16_rn(v.x), h1 = __float2bfloat16_rn(v.y);
    __nv_bfloat16 h2 = __float2bfloat16_rn(v.z), h3 = __float2bfloat16_rn(v.w);
    __nv_bfloat16 l0 = __float2bfloat16_rn(v.x - __bfloat162float(h0));
    __nv_bfloat16 l1 = __float2bfloat16_rn(v.y - __bfloat162float(h1));
    __nv_bfloat16 l2 = __float2bfloat16_rn(v.z - __bfloat162float(h2));
    __nv_bfloat16 l3 = __float2bfloat16_rn(v.w - __bfloat162float(h3));
    __nv_bfloat162* hp = (__nv_bfloat162*)hi;
    __nv_bfloat162* lp = (__nv_bfloat162*)lo;
    hp[i * 2 + 0] = __halves2bfloat162(h0, h1);
    hp[i * 2 + 1] = __halves2bfloat162(h2, h3);
    lp[i * 2 + 0] = __halves2bfloat162(l0, l1);
    lp[i * 2 + 1] = __halves2bfloat162(l2, l3);
}

// ---------------------------------------------------------------------------
// Fused transpose+split for all 4 weights (blockIdx.z selects)
// ---------------------------------------------------------------------------
__global__ __launch_bounds__(256) void transpose_split4_kernel(
    const float* __restrict__ W0, __nv_bfloat16* __restrict__ H0, __nv_bfloat16* __restrict__ L0,
    const float* __restrict__ W1, __nv_bfloat16* __restrict__ H1, __nv_bfloat16* __restrict__ L1,
    const float* __restrict__ W2, __nv_bfloat16* __restrict__ H2, __nv_bfloat16* __restrict__ L2,
    const float* __restrict__ W3, __nv_bfloat16* __restrict__ H3, __nv_bfloat16* __restrict__ L3)
{
    const int z = blockIdx.z;
    const float* W = (z == 0) ? W0 : (z == 1) ? W1 : (z == 2) ? W2 : W3;
    __nv_bfloat16* Thi = (z == 0) ? H0 : (z == 1) ? H1 : (z == 2) ? H2 : H3;
    __nv_bfloat16* Tlo = (z == 0) ? L0 : (z == 1) ? L1 : (z == 2) ? L2 : L3;

    __shared__ float tile[32][33];
    const int tx = threadIdx.x, ty = threadIdx.y;
    const int x = blockIdx.x * 32 + tx;
    const int y0 = blockIdx.y * 32;
#pragma unroll
    for (int j = ty; j < 32; j += 8)
        tile[j][tx] = W[(size_t)(y0 + j) * DMODEL + x];
    __syncthreads();
    const int x2 = y0 + tx;
    const int y2 = blockIdx.x * 32;
#pragma unroll
    for (int j = ty; j < 32; j += 8) {
        float v = tile[tx][j];
        __nv_bfloat16 h = __float2bfloat16_rn(v);
        __nv_bfloat16 l = __float2bfloat16_rn(v - __bfloat162float(h));
        Thi[(size_t)(y2 + j) * DMODEL + x2] = h;
        Tlo[(size_t)(y2 + j) * DMODEL + x2] = l;
    }
}

// ---------------------------------------------------------------------------
// bf16x3 GEMM body (3-stage cp.async pipeline, BK=32, CTA 128x128, 8 warps).
// MODE 0: fp32 output [M,N]. MODE 1: bf16 hi/lo head-split output.
// smem: 3 stages x {Ahi, Alo, Bhi, Blo} x 8KB = 96KB.
// ---------------------------------------------------------------------------
template <int MODE>
__device__ __forceinline__ void gemm_body(
    const __nv_bfloat16* __restrict__ Ahi, const __nv_bfloat16* __restrict__ Alo,
    const __nv_bfloat16* __restrict__ Bhi, const __nv_bfloat16* __restrict__ Blo,
    const float* __restrict__ bias, float* __restrict__ C,
    __nv_bfloat16* __restrict__ Chi, __nv_bfloat16* __restrict__ Clo,
    uint32_t sb, int m0, int n0)
{
    const int t    = threadIdx.x;
    const int lane = t & 31;
    const int wid  = t >> 5;
    const int wm   = wid >> 2;
    const int wn   = wid & 3;

    const __nv_bfloat16* b0p = Ahi + (size_t)m0 * DMODEL;
    const __nv_bfloat16* b1p = Alo + (size_t)m0 * DMODEL;
    const __nv_bfloat16* b2p = Bhi + (size_t)n0 * DMODEL;
    const __nv_bfloat16* b3p = Blo + (size_t)n0 * DMODEL;

    auto load_chunk = [&](int chunk, int stage) {
#pragma unroll
        for (int tile = 0; tile < 4; tile++) {
            const __nv_bfloat16* src =
                (tile == 0) ? b0p : (tile == 1) ? b1p : (tile == 2) ? b2p : b3p;
#pragma unroll
            for (int it = 0; it < 2; it++) {
                const int idx = t + it * 256;
                const int row = idx >> 2;
                const int col = idx & 3;
                const uint32_t pc  = (uint32_t)(col ^ ((row >> 1) & 3));
                const uint32_t dst = sb + (uint32_t)stage * 32768u +
                                     (uint32_t)tile * 8192u +
                                     (uint32_t)row * 64u + (pc << 4);
                CP_ASYNC16(dst, src + (size_t)row * DMODEL + chunk * 32 + col * 8);
            }
        }
        CP_COMMIT();
    };

    load_chunk(0, 0);
    load_chunk(1, 1);
    load_chunk(2, 2);

    float acc[4][4][4];
#pragma unroll
    for (int mf = 0; mf < 4; mf++)
#pragma unroll
        for (int nf = 0; nf < 4; nf++)
#pragma unroll
            for (int r = 0; r < 4; r++) acc[mf][nf][r] = 0.f;

    const int lrow  = lane & 15;
    const int lcolq = lane >> 4;

    int st = 0;
    for (int ch = 0; ch < 32; ch++) {
        if (ch < 29) CP_WAIT(2);
        else         CP_WAIT(0);
        __syncthreads();
        const uint32_t base = sb + (uint32_t)st * 32768u;

#pragma unroll
        for (int ks = 0; ks < 2; ks++) {
            uint32_t ahi[4][4], alo[4][4];
#pragma unroll
            for (int mf = 0; mf < 4; mf++) {
                const int row = wm * 64 + mf * 16 + lrow;
                const uint32_t pc  = (uint32_t)((ks * 2 + lcolq) ^ ((row >> 1) & 3));
                const uint32_t off = (uint32_t)row * 64u + (pc << 4);
                ldsm4(ahi[mf], base + off);
                ldsm4(alo[mf], base + 8192u + off);
            }
            uint32_t bhi[2][4], blo[2][4];
#pragma unroll
            for (int nq = 0; nq < 2; nq++) {
                const int row = wn * 32 + nq * 16 + lrow;
                const uint32_t pc  = (uint32_t)((ks * 2 + lcolq) ^ ((row >> 1) & 3));
                const uint32_t off = (uint32_t)row * 64u + (pc << 4);
                ldsm4(bhi[nq], base + 16384u + off);
                ldsm4(blo[nq], base + 24576u + off);
            }
#pragma unroll
            for (int mf = 0; mf < 4; mf++)
#pragma unroll
                for (int nf = 0; nf < 4; nf++) {
                    const int nq = nf >> 1, hh = nf & 1;
                    mma_bf16(acc[mf][nf], ahi[mf], bhi[nq][hh], bhi[nq][hh + 2]);
                    mma_bf16(acc[mf][nf], ahi[mf], blo[nq][hh], blo[nq][hh + 2]);
                    mma_bf16(acc[mf][nf], alo[mf], bhi[nq][hh], bhi[nq][hh + 2]);
                }
        }
        __syncthreads();
        if (ch + 3 < 32) load_chunk(ch + 3, st);
        st = (st == 2) ? 0 : st + 1;
    }

    const int gm = m0 + wm * 64;
    const int gn = n0 + wn * 32;
    const int g  = lane >> 2;
    const int c2 = (lane & 3) * 2;
#pragma unroll
    for (int mf = 0; mf < 4; mf++) {
#pragma unroll
        for (int nf = 0; nf < 4; nf++) {
            const int n = gn + nf * 8 + c2;
            const float bx = bias[n], by = bias[n + 1];
#pragma unroll
            for (int half = 0; half < 2; half++) {
                const int m = gm + mf * 16 + g + half * 8;
                float v0 = acc[mf][nf][half * 2 + 0] + bx;
                float v1 = acc[mf][nf][half * 2 + 1] + by;
                if (MODE == 1) {
                    const int b = m >> 11, s = m & (SEQ - 1);
                    const int h = n >> 6, kk = n & (HDIM - 1);
                    const size_t idx = (((size_t)((b * NHEAD + h) * SEQ + s)) << 6) + kk;
                    float h0 = __bfloat162float(__float2bfloat16_rn(v0));
                    float h1 = __bfloat162float(__float2bfloat16_rn(v1));
                    *(uint32_t*)&Chi[idx] = packbf2(h0, h1);
                    *(uint32_t*)&Clo[idx] = packbf2(v0 - h0, v1 - h1);
                } else {
                    *(float2*)(C + (size_t)m * DMODEL + n) = make_float2(v0, v1);
                }
            }
        }
    }
}

// Fused Q/K/V projection: blockIdx.z in {0,1,2} selects (A, W, bias, out).
__global__ __launch_bounds__(256, 2) void proj_gemm_kernel(
    const __nv_bfloat16* __restrict__ dh, const __nv_bfloat16* __restrict__ dl,
    const __nv_bfloat16* __restrict__ eh, const __nv_bfloat16* __restrict__ el,
    const __nv_bfloat16* __restrict__ wqh, const __nv_bfloat16* __restrict__ wql,
    const __nv_bfloat16* __restrict__ wkh, const __nv_bfloat16* __restrict__ wkl,
    const __nv_bfloat16* __restrict__ wvh, const __nv_bfloat16* __restrict__ wvl,
    const float* __restrict__ bq, const float* __restrict__ bk,
    const float* __restrict__ bv,
    __nv_bfloat16* __restrict__ qh, __nv_bfloat16* __restrict__ ql,
    __nv_bfloat16* __restrict__ kh, __nv_bfloat16* __restrict__ kl,
    __nv_bfloat16* __restrict__ vh, __nv_bfloat16* __restrict__ vl)
{
    extern __shared__ __align__(1024) char smem[];
    const int z = blockIdx.z;
    const __nv_bfloat16* Ahi = (z == 0) ? dh : eh;
    const __nv_bfloat16* Alo = (z == 0) ? dl : el;
    const __nv_bfloat16* Bhi = (z == 0) ? wqh : (z == 1) ? wkh : wvh;
    const __nv_bfloat16* Blo = (z == 0) ? wql : (z == 1) ? wkl : wvl;
    const float* bias        = (z == 0) ? bq  : (z == 1) ? bk  : bv;
    __nv_bfloat16* Chi       = (z == 0) ? qh  : (z == 1) ? kh  : vh;
    __nv_bfloat16* Clo       = (z == 0) ? ql  : (z == 1) ? kl  : vl;
    gemm_body<1>(Ahi, Alo, Bhi, Blo, bias, nullptr, Chi, Clo,
                 smem_to_u32(smem), blockIdx.y * 128, blockIdx.x * 128);
}

// Output projection: fp32 result.
__global__ __launch_bounds__(256, 2) void out_gemm_kernel(
    const __nv_bfloat16* __restrict__ Ahi, const __nv_bfloat16* __restrict__ Alo,
    const __nv_bfloat16* __restrict__ Bhi, const __nv_bfloat16* __restrict__ Blo,
    const float* __restrict__ bias, float* __restrict__ C)
{
    extern __shared__ __align__(1024) char smem[];
    gemm_body<0>(Ahi, Alo, Bhi, Blo, bias, C, nullptr, nullptr,
                 smem_to_u32(smem), blockIdx.y * 128, blockIdx.x * 128);
}

// ---------------------------------------------------------------------------
// Tensor-core causal flash attention (bf16x3 via mma.sync).
// CTA = (128-row Q tile, head, batch); heavy tiles scheduled first.
// ---------------------------------------------------------------------------
__global__ __launch_bounds__(256, 1) void attn_mma_kernel(
    const __nv_bfloat16* __restrict__ Qh, const __nv_bfloat16* __restrict__ Ql,
    const __nv_bfloat16* __restrict__ Kh, const __nv_bfloat16* __restrict__ Kl,
    const __nv_bfloat16* __restrict__ Vh, const __nv_bfloat16* __restrict__ Vl,
    __nv_bfloat16* __restrict__ Ch, __nv_bfloat16* __restrict__ Cl)
{
    extern __shared__ __align__(1024) char smem[];
    const uint32_t sb = smem_to_u32(smem);
    const int t    = threadIdx.x;
    const int lane = t & 31;
    const int w    = t >> 5;
    const int qt = gridDim.x - 1 - blockIdx.x;     // heavy-first
    const int h = blockIdx.y, b = blockIdx.z;
    const int q0 = qt * 128;

    const size_t headoff = (size_t)((b * NHEAD + h) * SEQ) * HDIM;
    const __nv_bfloat16* Qhp = Qh + headoff + (size_t)q0 * HDIM;
    const __nv_bfloat16* Qlp = Ql + headoff + (size_t)q0 * HDIM;
    const __nv_bfloat16* Khp = Kh + headoff;
    const __nv_bfloat16* Klp = Kl + headoff;
    const __nv_bfloat16* Vhp = Vh + headoff;
    const __nv_bfloat16* Vlp = Vl + headoff;

#pragma unroll
    for (int it = 0; it < 4; it++) {
        const int idx = t + it * 256;
        const int row = idx >> 3;
        const int c   = idx & 7;
        const uint32_t pc = (uint32_t)(c ^ (row & 7));
        const uint32_t off = (uint32_t)row * 128u + (pc << 4);
        CP_ASYNC16(sb + off,          Qhp + (size_t)row * HDIM + c * 8);
        CP_ASYNC16(sb + 16384u + off, Qlp + (size_t)row * HDIM + c * 8);
    }
    CP_COMMIT();

    auto load_kv = [&](int step, int stage) {
        const int c0 = step * 64;
        const __nv_bfloat16* srcs[4] = {
            Khp + (size_t)c0 * HDIM, Klp + (size_t)c0 * HDIM,
            Vhp + (size_t)c0 * HDIM, Vlp + (size_t)c0 * HDIM };
#pragma unroll
        for (int tile = 0; tile < 4; tile++) {
#pragma unroll
            for (int it = 0; it < 2; it++) {
                const int idx = t + it * 256;
                const int row = idx >> 3;
                const int c   = idx & 7;
                const uint32_t pc = (uint32_t)(c ^ (row & 7));
                const uint32_t dst = sb + 32768u + (uint32_t)stage * 32768u +
                                     (uint32_t)tile * 8192u +
                                     (uint32_t)row * 128u + (pc << 4);
                CP_ASYNC16(dst, srcs[tile] + (size_t)row * HDIM + c * 8);
            }
        }
        CP_COMMIT();
    };

    const int nkv = 2 * qt + 2;
    load_kv(0, 0);
    load_kv(1, 1);

    CP_WAIT(2);
    __syncthreads();
    uint32_t qhi[4][4], qlo[4][4];
#pragma unroll
    for (int kb = 0; kb < 4; kb++) {
        const int row = w * 16 + (lane & 15);
        const uint32_t pc = (uint32_t)((kb * 2 + (lane >> 4)) ^ (row & 7));
        const uint32_t off = (uint32_t)row * 128u + (pc << 4);
        ldsm4(qhi[kb], sb + off);
        ldsm4(qlo[kb], sb + 16384u + off);
    }

    float m_i[2] = {-1e30f, -1e30f};
    float l_i[2] = {0.f, 0.f};
    float o[8][4];
#pragma unroll
    for (int n8 = 0; n8 < 8; n8++)
#pragma unroll
        for (int r = 0; r < 4; r++) o[n8][r] = 0.f;

    const float SC = 0.18033688011112042f;   // log2(e) / 8
    const int g   = lane >> 2;
    const int c2  = (lane & 3) * 2;
    const int wrow = q0 + w * 16;

    for (int i = 0; i < nkv; i++) {
        const int st = i & 1;
        if (i < nkv - 2) CP_WAIT(1);
        else             CP_WAIT(0);
        __syncthreads();
        const int c0 = i * 64;
        const bool skip = (c0 > wrow + 15);
        if (!skip) {
            const uint32_t kvb = sb + 32768u + (uint32_t)st * 32768u;
            float sacc[8][4];
#pragma unroll
            for (int n8 = 0; n8 < 8; n8++)
#pragma unroll
                for (int r = 0; r < 4; r++) sacc[n8][r] = 0.f;
#pragma unroll
            for (int kb = 0; kb < 4; kb++) {
#pragma unroll
                for (int nb = 0; nb < 4; nb++) {
                    uint32_t kf[4], kf2[4];
                    const int row = nb * 16 + (lane & 15);
                    const uint32_t pc = (uint32_t)((kb * 2 + (lane >> 4)) ^ (row & 7));
                    const uint32_t off = (uint32_t)row * 128u + (pc << 4);
                    ldsm4(kf,  kvb + off);
                    ldsm4(kf2, kvb + 8192u + off);
                    mma_bf16(sacc[2 * nb],     qhi[kb], kf[0],  kf[2]);
                    mma_bf16(sacc[2 * nb],     qhi[kb], kf2[0], kf2[2]);
                    mma_bf16(sacc[2 * nb],     qlo[kb], kf[0],  kf[2]);
                    mma_bf16(sacc[2 * nb + 1], qhi[kb], kf[1],  kf[3]);
                    mma_bf16(sacc[2 * nb + 1], qhi[kb], kf2[1], kf2[3]);
                    mma_bf16(sacc[2 * nb + 1], qlo[kb], kf[1],  kf[3]);
                }
            }
            const bool needmask = (c0 + 63 > wrow);
            const int row0 = wrow + g, row1 = row0 + 8;
#pragma unroll
            for (int n8 = 0; n8 < 8; n8++) {
                const int col = c0 + n8 * 8 + c2;
#pragma unroll
                for (int r = 0; r < 4; r++) {
                    float v = sacc[n8][r] * SC;
                    if (needmask) {
                        const int cc = col + (r & 1);
                        const int rr = (r < 2) ? row0 : row1;
                        if (cc > rr) v = -1e30f;
                    }
                    sacc[n8][r] = v;
                }
            }
            float mx0 = -1e30f, mx1 = -1e30f;
#pragma unroll
            for (int n8 = 0; n8 < 8; n8++) {
                mx0 = fmaxf(mx0, fmaxf(sacc[n8][0], sacc[n8][1]));
                mx1 = fmaxf(mx1, fmaxf(sacc[n8][2], sacc[n8][3]));
            }
            mx0 = fmaxf(mx0, __shfl_xor_sync(0xffffffffu, mx0, 1));
            mx0 = fmaxf(mx0, __shfl_xor_sync(0xffffffffu, mx0, 2));
            mx1 = fmaxf(mx1, __shfl_xor_sync(0xffffffffu, mx1, 1));
            mx1 = fmaxf(mx1, __shfl_xor_sync(0xffffffffu, mx1, 2));
            const float mn0 = fmaxf(m_i[0], mx0);
            const float mn1 = fmaxf(m_i[1], mx1);
            const float sc0 = exp2f(m_i[0] - mn0);
            const float sc1 = exp2f(m_i[1] - mn1);
            float sum0 = 0.f, sum1 = 0.f;
#pragma unroll
            for (int n8 = 0; n8 < 8; n8++) {
                sacc[n8][0] = exp2f(sacc[n8][0] - mn0);
                sacc[n8][1] = exp2f(sacc[n8][1] - mn0);
                sacc[n8][2] = exp2f(sacc[n8][2] - mn1);
                sacc[n8][3] = exp2f(sacc[n8][3] - mn1);
                sum0 += sacc[n8][0] + sacc[n8][1];
                sum1 += sacc[n8][2] + sacc[n8][3];
            }
            sum0 += __shfl_xor_sync(0xffffffffu, sum0, 1);
            sum0 += __shfl_xor_sync(0xffffffffu, sum0, 2);
            sum1 += __shfl_xor_sync(0xffffffffu, sum1, 1);
            sum1 += __shfl_xor_sync(0xffffffffu, sum1, 2);
            l_i[0] = l_i[0] * sc0 + sum0;  m_i[0] = mn0;
            l_i[1] = l_i[1] * sc1 + sum1;  m_i[1] = mn1;
#pragma unroll
            for (int n8 = 0; n8 < 8; n8++) {
                o[n8][0] *= sc0; o[n8][1] *= sc0;
                o[n8][2] *= sc1; o[n8][3] *= sc1;
            }
            uint32_t phi[4][4], plo[4][4];
#pragma unroll
            for (int kb = 0; kb < 4; kb++) {
#pragma unroll
                for (int q = 0; q < 2; q++) {
                    const float v0 = sacc[2 * kb][2 * q], v1 = sacc[2 * kb][2 * q + 1];
                    const float v2 = sacc[2 * kb + 1][2 * q], v3 = sacc[2 * kb + 1][2 * q + 1];
                    const float h0 = __bfloat162float(__float2bfloat16_rn(v0));
                    const float h1 = __bfloat162float(__float2bfloat16_rn(v1));
                    const float h2 = __bfloat162float(__float2bfloat16_rn(v2));
                    const float h3 = __bfloat162float(__float2bfloat16_rn(v3));
                    phi[kb][q]     = packbf2(h0, h1);
                    phi[kb][q + 2] = packbf2(h2, h3);
                    plo[kb][q]     = packbf2(v0 - h0, v1 - h1);
                    plo[kb][q + 2] = packbf2(v2 - h2, v3 - h3);
                }
            }
#pragma unroll
            for (int kb = 0; kb < 4; kb++) {
#pragma unroll
                for (int nb = 0; nb < 4; nb++) {
                    uint32_t vf[4], vf2[4];
                    const int row = kb * 16 + (lane & 15);
                    const uint32_t pc = (uint32_t)((nb * 2 + (lane >> 4)) ^ (row & 7));
                    const uint32_t off = (uint32_t)row * 128u + (pc << 4);
                    ldsm4t(vf,  kvb + 16384u + off);
                    ldsm4t(vf2, kvb + 24576u + off);
                    mma_bf16(o[2 * nb],     phi[kb], vf[0],  vf[1]);
                    mma_bf16(o[2 * nb],     phi[kb], vf2[0], vf2[1]);
                    mma_bf16(o[2 * nb],     plo[kb], vf[0],  vf[1]);
                    mma_bf16(o[2 * nb + 1], phi[kb], vf[2],  vf[3]);
                    mma_bf16(o[2 * nb + 1], phi[kb], vf2[2], vf2[3]);
                    mma_bf16(o[2 * nb + 1], plo[kb], vf[2],  vf[3]);
                }
            }
        }
        __syncthreads();
        if (i + 2 < nkv) load_kv(i + 2, st);
    }

    const float inv0 = 1.f / l_i[0];
    const float inv1 = 1.f / l_i[1];
    const int row0 = q0 + w * 16 + g;
    const size_t base0 = ((size_t)(b * SEQ + row0)) * DMODEL + h * HDIM;
    const size_t base1 = base0 + (size_t)8 * DMODEL;
#pragma unroll
    for (int n8 = 0; n8 < 8; n8++) {
        const int col = n8 * 8 + c2;
        float v0 = o[n8][0] * inv0, v1 = o[n8][1] * inv0;
        float v2 = o[n8][2] * inv1, v3 = o[n8][3] * inv1;
        float h0 = __bfloat162float(__float2bfloat16_rn(v0));
        float h1 = __bfloat162float(__float2bfloat16_rn(v1));
        float h2 = __bfloat162float(__float2bfloat16_rn(v2));
        float h3 = __bfloat162float(__float2bfloat16_rn(v3));
        *(uint32_t*)&Ch[base0 + col] = packbf2(h0, h1);
        *(uint32_t*)&Cl[base0 + col] = packbf2(v0 - h0, v1 - h1);
        *(uint32_t*)&Ch[base1 + col] = packbf2(h2, h3);
        *(uint32_t*)&Cl[base1 + col] = packbf2(v2 - h2, v3 - h3);
    }
}

// ---------------------------------------------------------------------------
extern "C" void kernel_launch(void* const* d_in, const int* in_sizes, int n_in,
                              void* d_out, int out_size)
{
    const float* dec = (const float*)d_in[0];
    const float* enc = (const float*)d_in[1];
    // d_in[2] = mask (causal tril; implemented analytically)
    const float* Wq = (const float*)d_in[3];
    const float* bq = (const float*)d_in[4];
    const float* Wk = (const float*)d_in[5];
    const float* bk = (const float*)d_in[6];
    const float* Wv = (const float*)d_in[7];
    const float* bv = (const float*)d_in[8];
    const float* Wo = (const float*)d_in[9];
    const float* bo = (const float*)d_in[10];

    __nv_bfloat16 *qh, *ql, *kh, *kl, *vh, *vl, *cth, *ctl;
    __nv_bfloat16 *dh, *dl, *eh, *el;
    __nv_bfloat16 *wqh, *wql, *wkh, *wkl, *wvh, *wvl, *woh, *wol;
    cudaGetSymbolAddress((void**)&qh,  g_Qh);
    cudaGetSymbolAddress((void**)&ql,  g_Ql);
    cudaGetSymbolAddress((void**)&kh,  g_Kh);
    cudaGetSymbolAddress((void**)&kl,  g_Kl);
    cudaGetSymbolAddress((void**)&vh,  g_Vh);
    cudaGetSymbolAddress((void**)&vl,  g_Vl);
    cudaGetSymbolAddress((void**)&cth, g_cth);
    cudaGetSymbolAddress((void**)&ctl, g_ctl);
    cudaGetSymbolAddress((void**)&dh,  g_dec_hi);
    cudaGetSymbolAddress((void**)&dl,  g_dec_lo);
    cudaGetSymbolAddress((void**)&eh,  g_enc_hi);
    cudaGetSymbolAddress((void**)&el,  g_enc_lo);
    cudaGetSymbolAddress((void**)&wqh, g_Wq_hi);
    cudaGetSymbolAddress((void**)&wql, g_Wq_lo);
    cudaGetSymbolAddress((void**)&wkh, g_Wk_hi);
    cudaGetSymbolAddress((void**)&wkl, g_Wk_lo);
    cudaGetSymbolAddress((void**)&wvh, g_Wv_hi);
    cudaGetSymbolAddress((void**)&wvl, g_Wv_lo);
    cudaGetSymbolAddress((void**)&woh, g_Wo_hi);
    cudaGetSymbolAddress((void**)&wol, g_Wo_lo);

    // Fused conversions
    split2_kernel<<<dim3(NELEM_ACT / 1024, 2), 256>>>(dec, dh, dl, enc, eh, el,
                                                      NELEM_ACT / 4);
    transpose_split4_kernel<<<dim3(32, 32, 4), dim3(32, 8)>>>(
        Wq, wqh, wql, Wk, wkh, wkl, Wv, wvh, wvl, Wo, woh, wol);

    // Fused Q/K/V projections (one launch, 768 CTAs)
    const int gsm = 98304;
    cudaFuncSetAttribute(proj_gemm_kernel, cudaFuncAttributeMaxDynamicSharedMemorySize, gsm);
    cudaFuncSetAttribute(out_gemm_kernel,  cudaFuncAttributeMaxDynamicSharedMemorySize, gsm);
    proj_gemm_kernel<<<dim3(DMODEL / 128, MTOT / 128, 3), 256, gsm>>>(
        dh, dl, eh, el, wqh, wql, wkh, wkl, wvh, wvl,
        bq, bk, bv, qh, ql, kh, kl, vh, vl);

    // Tensor-core flash attention (heavy-first)
    const int asm_bytes = 32768 + 2 * 32768;
    cudaFuncSetAttribute(attn_mma_kernel, cudaFuncAttributeMaxDynamicSharedMemorySize, asm_bytes);
    attn_mma_kernel<<<dim3(SEQ / 128, NHEAD, BATCH), 256, asm_bytes>>>(
        qh, ql, kh, kl, vh, vl, cth, ctl);

    // Output projection
    out_gemm_kernel<<<dim3(DMODEL / 128, MTOT / 128), 256, gsm>>>(
        cth, ctl, woh, wol, bo, (float*)d_out);
}